// round 2
// baseline (speedup 1.0000x reference)
#include <cuda_runtime.h>
#include <cstdint>

#define N_NODES   100000
#define N_EDGES   800000
#define HIDF      128
#define EMBF      64
#define OUTF      8
#define N_GRAPHS  64

// ---------------- scratch (device globals; no allocation) ----------------
__device__ int   g_is64;
__device__ int   g_src[N_EDGES];
__device__ int   g_dst[N_EDGES];
__device__ int   g_batch[N_NODES];
__device__ int   g_deg[N_NODES];
__device__ int   g_off[N_NODES];
__device__ int   g_cur[N_NODES];
__device__ int   g_csr[N_EDGES];
__device__ float g_agg[(size_t)N_NODES * HIDF];
__device__ float g_h1 [(size_t)N_NODES * HIDF];
__device__ float g_h2 [(size_t)N_NODES * HIDF];
__device__ float g_wc1[256 * HIDF];
__device__ float g_wc2[256 * HIDF];
__device__ float g_pool[N_GRAPHS * HIDF];
__device__ int   g_cnt[N_GRAPHS];

// ---------------- dtype detection (int64 vs int32 indices) ----------------
__global__ void k_detect(const unsigned int* __restrict__ w) {
    __shared__ int flag;
    if (threadIdx.x == 0) flag = 0;
    __syncthreads();
    for (int i = 1 + (int)threadIdx.x * 2; i < 4096; i += blockDim.x * 2)
        if (w[i] != 0u) atomicOr(&flag, 1);
    __syncthreads();
    if (threadIdx.x == 0) g_is64 = (flag == 0) ? 1 : 0;
}

__global__ void k_convert_edges(const void* __restrict__ ei) {
    int i = blockIdx.x * blockDim.x + threadIdx.x;
    if (i >= N_EDGES) return;
    if (g_is64) {
        const long long* p = (const long long*)ei;
        g_src[i] = (int)p[i];
        g_dst[i] = (int)p[N_EDGES + i];
    } else {
        const int* p = (const int*)ei;
        g_src[i] = p[i];
        g_dst[i] = p[N_EDGES + i];
    }
}

__global__ void k_convert_batch(const void* __restrict__ b) {
    int i = blockIdx.x * blockDim.x + threadIdx.x;
    if (i >= N_NODES) return;
    if (g_is64) g_batch[i] = (int)((const long long*)b)[i];
    else        g_batch[i] = ((const int*)b)[i];
    g_deg[i] = 0;
    if (i < N_GRAPHS * HIDF) g_pool[i] = 0.f;
    if (i < N_GRAPHS)        g_cnt[i]  = 0;
}

// ---------------- CSR build ----------------
__global__ void k_hist() {
    int i = blockIdx.x * blockDim.x + threadIdx.x;
    if (i < N_EDGES) atomicAdd(&g_deg[g_dst[i]], 1);
}

__global__ void k_scan() {  // one block, 1024 threads
    __shared__ int ssum[1024];
    const int CH = 98;
    int t = threadIdx.x;
    int lo = t * CH, hi = min(lo + CH, N_NODES);
    int s = 0;
    for (int i = lo; i < hi; i++) s += g_deg[i];
    ssum[t] = s;
    __syncthreads();
    for (int o = 1; o < 1024; o <<= 1) {
        int v = (t >= o) ? ssum[t - o] : 0;
        __syncthreads();
        ssum[t] += v;
        __syncthreads();
    }
    int base = ssum[t] - s;
    for (int i = lo; i < hi; i++) {
        g_off[i] = base;
        g_cur[i] = base;
        base += g_deg[i];
    }
}

__global__ void k_fill() {
    int i = blockIdx.x * blockDim.x + threadIdx.x;
    if (i >= N_EDGES) return;
    int d = g_dst[i];
    int p = atomicAdd(&g_cur[d], 1);
    g_csr[p] = g_src[i];
}

// ---------------- mean aggregation: one warp per node ----------------
__global__ void k_aggregate(const float* __restrict__ H, float* __restrict__ A) {
    int node = (blockIdx.x * blockDim.x + threadIdx.x) >> 5;
    int lane = threadIdx.x & 31;
    if (node >= N_NODES) return;
    int start = g_off[node];
    int d = g_deg[node];
    float4 acc = make_float4(0.f, 0.f, 0.f, 0.f);
    for (int e = 0; e < d; e++) {
        int s = g_csr[start + e];
        float4 v = ((const float4*)(H + (size_t)s * HIDF))[lane];
        acc.x += v.x; acc.y += v.y; acc.z += v.z; acc.w += v.w;
    }
    float inv = 1.0f / (float)max(d, 1);
    acc.x *= inv; acc.y *= inv; acc.z *= inv; acc.w *= inv;
    ((float4*)(A + (size_t)node * HIDF))[lane] = acc;
}

// ---------------- weight concat (K-major [256][128]) ----------------
__global__ void k_prep(const float* __restrict__ W1l, const float* __restrict__ W1r,
                       const float* __restrict__ W2l, const float* __restrict__ W2r,
                       float* __restrict__ wc1, float* __restrict__ wc2) {
    int idx = blockIdx.x * blockDim.x + threadIdx.x;
    if (idx >= 256 * HIDF) return;
    int k = idx >> 7, j = idx & 127;
    wc1[idx] = (k < 128) ? W1l[j * 128 + k] : W1r[j * 128 + (k - 128)];
    wc2[idx] = (k < 128) ? W2l[j * 128 + k] : W2r[j * 128 + (k - 128)];
}

// ---------------- 3xTF32 tensor-core GEMM ----------------
// relu(agg@Wl^T + h@Wr^T + b): M=100000, N=128, K=256 (first 128 k from Agg,
// next 128 from Hin). Block 128x128, BK=16, 8 warps (2M x 4N), warp tile
// 64x32 via mma.sync.m16n8k8.tf32. Inputs split a=hi+lo (tf32); accumulate
// hi*hi + hi*lo + lo*hi for ~fp32 accuracy.
#define LDSW 136  // smem row stride (floats): conflict-free frag loads

__device__ __forceinline__ void split_tf32(float v, float& hi, float& lo) {
    unsigned h, l;
    asm("cvt.rna.tf32.f32 %0, %1;" : "=r"(h) : "f"(v));
    float hf = __uint_as_float(h);
    float r = v - hf;
    asm("cvt.rna.tf32.f32 %0, %1;" : "=r"(l) : "f"(r));
    hi = hf;
    lo = __uint_as_float(l);
}

__device__ __forceinline__ void mma_tf32(float* c, const unsigned* a, const unsigned* b) {
    asm volatile(
        "mma.sync.aligned.m16n8k8.row.col.f32.tf32.tf32.f32 "
        "{%0,%1,%2,%3}, {%4,%5,%6,%7}, {%8,%9}, {%0,%1,%2,%3};"
        : "+f"(c[0]), "+f"(c[1]), "+f"(c[2]), "+f"(c[3])
        : "r"(a[0]), "r"(a[1]), "r"(a[2]), "r"(a[3]), "r"(b[0]), "r"(b[1]));
}

__global__ void __launch_bounds__(256)
k_gemm_tc(const float* __restrict__ Agg, const float* __restrict__ Hin,
          const float* __restrict__ Wc, const float* __restrict__ bias,
          float* __restrict__ Hout) {
    __shared__ float Ahi[16 * LDSW], Alo[16 * LDSW];
    __shared__ float Bhi[16 * LDSW], Blo[16 * LDSW];
    __shared__ float bsh[128];
    int tid = threadIdx.x;
    int warp = tid >> 5, lane = tid & 31;
    int wm = warp & 1, wn = warp >> 1;        // 2 x 4 warp grid
    int gq = lane >> 2, tig = lane & 3;       // quad-pair layout
    int row0 = blockIdx.x * 128;
    if (tid < 128) bsh[tid] = bias[tid];

    float acc[4][4][4];
#pragma unroll
    for (int mi = 0; mi < 4; mi++)
#pragma unroll
        for (int ni = 0; ni < 4; ni++)
#pragma unroll
            for (int r = 0; r < 4; r++) acc[mi][ni][r] = 0.f;

    for (int k0 = 0; k0 < 256; k0 += 16) {
        const float* S = (k0 < 128) ? Agg : Hin;
        int kc = k0 & 127;
        // stage A: 128 rows x 16 k, split + transposed [k][m]
#pragma unroll
        for (int i = 0; i < 2; i++) {
            int idx = tid + i * 256;
            int r = idx >> 2, c = (idx & 3) * 4;
            int row = row0 + r;
            float4 v = make_float4(0.f, 0.f, 0.f, 0.f);
            if (row < N_NODES)
                v = *(const float4*)(S + (size_t)row * HIDF + kc + c);
            float vv[4] = {v.x, v.y, v.z, v.w};
#pragma unroll
            for (int j = 0; j < 4; j++) {
                float h, l;
                split_tf32(vv[j], h, l);
                Ahi[(c + j) * LDSW + r] = h;
                Alo[(c + j) * LDSW + r] = l;
            }
        }
        // stage B: 16 k x 128 n, split, [k][n]
#pragma unroll
        for (int i = 0; i < 2; i++) {
            int idx = tid + i * 256;
            int kk = idx >> 5, n = (idx & 31) * 4;
            float4 v = *(const float4*)(Wc + (size_t)(k0 + kk) * HIDF + n);
            float vv[4] = {v.x, v.y, v.z, v.w};
#pragma unroll
            for (int j = 0; j < 4; j++) {
                float h, l;
                split_tf32(vv[j], h, l);
                Bhi[kk * LDSW + n + j] = h;
                Blo[kk * LDSW + n + j] = l;
            }
        }
        __syncthreads();
#pragma unroll
        for (int ks = 0; ks < 2; ks++) {
            int kb = ks * 8;
            unsigned ah[4][4], al[4][4], bh[4][2], bl[4][2];
#pragma unroll
            for (int mi = 0; mi < 4; mi++) {
                int m = wm * 64 + mi * 16 + gq;
#pragma unroll
                for (int h = 0; h < 2; h++) {
                    int kr = (kb + tig + h * 4) * LDSW;
                    ah[mi][h * 2 + 0] = __float_as_uint(Ahi[kr + m]);
                    ah[mi][h * 2 + 1] = __float_as_uint(Ahi[kr + m + 8]);
                    al[mi][h * 2 + 0] = __float_as_uint(Alo[kr + m]);
                    al[mi][h * 2 + 1] = __float_as_uint(Alo[kr + m + 8]);
                }
            }
            // NB: fragment order for m16n8k8 A: {a0,a1,a2,a3} =
            // {(g,tig),(g+8,tig),(g,tig+4),(g+8,tig+4)} -> matches h-loop above
#pragma unroll
            for (int ni = 0; ni < 4; ni++) {
                int n = wn * 32 + ni * 8 + gq;
                bh[ni][0] = __float_as_uint(Bhi[(kb + tig) * LDSW + n]);
                bh[ni][1] = __float_as_uint(Bhi[(kb + tig + 4) * LDSW + n]);
                bl[ni][0] = __float_as_uint(Blo[(kb + tig) * LDSW + n]);
                bl[ni][1] = __float_as_uint(Blo[(kb + tig + 4) * LDSW + n]);
            }
#pragma unroll
            for (int mi = 0; mi < 4; mi++)
#pragma unroll
                for (int ni = 0; ni < 4; ni++) {
                    mma_tf32(acc[mi][ni], ah[mi], bh[ni]);
                    mma_tf32(acc[mi][ni], ah[mi], bl[ni]);
                    mma_tf32(acc[mi][ni], al[mi], bh[ni]);
                }
        }
        __syncthreads();
    }
    // epilogue: c0,c1 at (g, 2*tig), c2,c3 at (g+8, 2*tig)
#pragma unroll
    for (int mi = 0; mi < 4; mi++) {
#pragma unroll
        for (int ni = 0; ni < 4; ni++) {
            int colc = wn * 32 + ni * 8 + tig * 2;
            int ra = row0 + wm * 64 + mi * 16 + gq;
            int rb = ra + 8;
            if (ra < N_NODES) {
                Hout[(size_t)ra * HIDF + colc]     = fmaxf(acc[mi][ni][0] + bsh[colc], 0.f);
                Hout[(size_t)ra * HIDF + colc + 1] = fmaxf(acc[mi][ni][1] + bsh[colc + 1], 0.f);
            }
            if (rb < N_NODES) {
                Hout[(size_t)rb * HIDF + colc]     = fmaxf(acc[mi][ni][2] + bsh[colc], 0.f);
                Hout[(size_t)rb * HIDF + colc + 1] = fmaxf(acc[mi][ni][3] + bsh[colc + 1], 0.f);
            }
        }
    }
}

// ---------------- sorted segment-mean pooling ----------------
__global__ void k_pool(const float* __restrict__ H) {
    int t = threadIdx.x;
    int base = blockIdx.x * 512;
    if (base >= N_NODES) return;
    int end = min(base + 512, N_NODES);
    int cur = g_batch[base];
    float acc = 0.f;
    int run = 0;
    for (int n = base; n < end; n++) {
        int g = g_batch[n];
        if (g != cur) {
            atomicAdd(&g_pool[cur * HIDF + t], acc);
            if (t == 0) atomicAdd(&g_cnt[cur], run);
            acc = 0.f; run = 0; cur = g;
        }
        acc += H[(size_t)n * HIDF + t];
        run++;
    }
    atomicAdd(&g_pool[cur * HIDF + t], acc);
    if (t == 0) atomicAdd(&g_cnt[cur], run);
}

// ---------------- head ----------------
__global__ void k_head(const float* __restrict__ embed, const float* __restrict__ Wlin,
                       const float* __restrict__ blin, float* __restrict__ out) {
    int t = threadIdx.x;
    if (t >= N_GRAPHS * OUTF) return;
    int g = t >> 3, o = t & 7;
    float c = (float)max(g_cnt[g], 1);
    float inv = 1.0f / c;
    const float* wr = Wlin + o * (HIDF + EMBF);
    float s = 0.f;
    for (int k = 0; k < HIDF; k++) s += g_pool[g * HIDF + k] * inv * wr[k];
    for (int k = 0; k < EMBF; k++) s += embed[g * EMBF + k] * wr[HIDF + k];
    out[g * OUTF + o] = s + blin[o];
}

// ---------------- launch ----------------
extern "C" void kernel_launch(void* const* d_in, const int* in_sizes, int n_in,
                              void* d_out, int out_size) {
    const float* x     = (const float*)d_in[0];
    const void*  ei    = d_in[1];
    const void*  batch = d_in[2];
    const float* embed = (const float*)d_in[3];
    const float* W1l   = (const float*)d_in[4];
    const float* b1l   = (const float*)d_in[5];
    const float* W1r   = (const float*)d_in[6];
    const float* W2l   = (const float*)d_in[7];
    const float* b2l   = (const float*)d_in[8];
    const float* W2r   = (const float*)d_in[9];
    const float* Wlin  = (const float*)d_in[10];
    const float* blin  = (const float*)d_in[11];
    float* out = (float*)d_out;

    float *agg_p, *h1_p, *h2_p, *wc1_p, *wc2_p;
    cudaGetSymbolAddress((void**)&agg_p, g_agg);
    cudaGetSymbolAddress((void**)&h1_p,  g_h1);
    cudaGetSymbolAddress((void**)&h2_p,  g_h2);
    cudaGetSymbolAddress((void**)&wc1_p, g_wc1);
    cudaGetSymbolAddress((void**)&wc2_p, g_wc2);

    const int TB = 256;
    k_detect<<<1, 256>>>((const unsigned int*)ei);
    k_convert_edges<<<(N_EDGES + TB - 1) / TB, TB>>>(ei);
    k_convert_batch<<<(N_NODES + TB - 1) / TB, TB>>>(batch);
    k_hist<<<(N_EDGES + TB - 1) / TB, TB>>>();
    k_scan<<<1, 1024>>>();
    k_fill<<<(N_EDGES + TB - 1) / TB, TB>>>();
    k_prep<<<(256 * HIDF + TB - 1) / TB, TB>>>(W1l, W1r, W2l, W2r, wc1_p, wc2_p);

    // layer 1
    k_aggregate<<<(N_NODES + 7) / 8, 256>>>(x, agg_p);
    k_gemm_tc<<<(N_NODES + 127) / 128, 256>>>(agg_p, x, wc1_p, b1l, h1_p);
    // layer 2
    k_aggregate<<<(N_NODES + 7) / 8, 256>>>(h1_p, agg_p);
    k_gemm_tc<<<(N_NODES + 127) / 128, 256>>>(agg_p, h1_p, wc2_p, b2l, h2_p);
    // pooling + head
    k_pool<<<(N_NODES + 511) / 512, 128>>>(h2_p);
    k_head<<<1, 512>>>(embed, Wlin, blin, out);
}

// round 4
// speedup vs baseline: 1.7159x; 1.7159x over previous
#include <cuda_runtime.h>
#include <cstdint>

#define N_NODES   100000
#define N_EDGES   800000
#define HIDF      128
#define EMBF      64
#define OUTF      8
#define N_GRAPHS  64

// ---------------- scratch (device globals; no allocation) ----------------
__device__ int   g_is64;
__device__ int   g_src[N_EDGES];
__device__ int   g_dst[N_EDGES];
__device__ int   g_batch[N_NODES];
__device__ int   g_deg[N_NODES];
__device__ int   g_off[N_NODES];
__device__ int   g_cur[N_NODES];
__device__ int   g_csr[N_EDGES];
__device__ float g_agg[(size_t)N_NODES * HIDF];
__device__ float g_h1 [(size_t)N_NODES * HIDF];
__device__ float g_h2 [(size_t)N_NODES * HIDF];
// weights pre-split to bf16 hi/lo, layout [128 out][256 k] row-major
__device__ unsigned short g_wh1[128 * 256];
__device__ unsigned short g_wl1[128 * 256];
__device__ unsigned short g_wh2[128 * 256];
__device__ unsigned short g_wl2[128 * 256];
__device__ float g_pool[N_GRAPHS * HIDF];
__device__ int   g_cnt[N_GRAPHS];

// ---------------- dtype detection (int64 vs int32 indices) ----------------
__global__ void k_detect(const unsigned int* __restrict__ w) {
    __shared__ int flag;
    if (threadIdx.x == 0) flag = 0;
    __syncthreads();
    for (int i = 1 + (int)threadIdx.x * 2; i < 4096; i += blockDim.x * 2)
        if (w[i] != 0u) atomicOr(&flag, 1);
    __syncthreads();
    if (threadIdx.x == 0) g_is64 = (flag == 0) ? 1 : 0;
}

__global__ void k_convert_edges(const void* __restrict__ ei) {
    int i = blockIdx.x * blockDim.x + threadIdx.x;
    if (i >= N_EDGES) return;
    if (g_is64) {
        const long long* p = (const long long*)ei;
        g_src[i] = (int)p[i];
        g_dst[i] = (int)p[N_EDGES + i];
    } else {
        const int* p = (const int*)ei;
        g_src[i] = p[i];
        g_dst[i] = p[N_EDGES + i];
    }
}

__global__ void k_convert_batch(const void* __restrict__ b) {
    int i = blockIdx.x * blockDim.x + threadIdx.x;
    if (i >= N_NODES) return;
    if (g_is64) g_batch[i] = (int)((const long long*)b)[i];
    else        g_batch[i] = ((const int*)b)[i];
    g_deg[i] = 0;
    if (i < N_GRAPHS * HIDF) g_pool[i] = 0.f;
    if (i < N_GRAPHS)        g_cnt[i]  = 0;
}

// ---------------- CSR build ----------------
__global__ void k_hist() {
    int i = blockIdx.x * blockDim.x + threadIdx.x;
    if (i < N_EDGES) atomicAdd(&g_deg[g_dst[i]], 1);
}

__global__ void k_scan() {  // one block, 1024 threads
    __shared__ int ssum[1024];
    const int CH = 98;
    int t = threadIdx.x;
    int lo = t * CH, hi = min(lo + CH, N_NODES);
    int s = 0;
    for (int i = lo; i < hi; i++) s += g_deg[i];
    ssum[t] = s;
    __syncthreads();
    for (int o = 1; o < 1024; o <<= 1) {
        int v = (t >= o) ? ssum[t - o] : 0;
        __syncthreads();
        ssum[t] += v;
        __syncthreads();
    }
    int base = ssum[t] - s;
    for (int i = lo; i < hi; i++) {
        g_off[i] = base;
        g_cur[i] = base;
        base += g_deg[i];
    }
}

__global__ void k_fill() {
    int i = blockIdx.x * blockDim.x + threadIdx.x;
    if (i >= N_EDGES) return;
    int d = g_dst[i];
    int p = atomicAdd(&g_cur[d], 1);
    g_csr[p] = g_src[i];
}

// ---------------- mean aggregation: one warp per node ----------------
__global__ void k_aggregate(const float* __restrict__ H, float* __restrict__ A) {
    int node = (blockIdx.x * blockDim.x + threadIdx.x) >> 5;
    int lane = threadIdx.x & 31;
    if (node >= N_NODES) return;
    int start = g_off[node];
    int d = g_deg[node];
    float4 acc = make_float4(0.f, 0.f, 0.f, 0.f);
    for (int e = 0; e < d; e++) {
        int s = g_csr[start + e];
        float4 v = ((const float4*)(H + (size_t)s * HIDF))[lane];
        acc.x += v.x; acc.y += v.y; acc.z += v.z; acc.w += v.w;
    }
    float inv = 1.0f / (float)max(d, 1);
    acc.x *= inv; acc.y *= inv; acc.z *= inv; acc.w *= inv;
    ((float4*)(A + (size_t)node * HIDF))[lane] = acc;
}

// ---------------- weight prep: concat + bf16 hi/lo split ----------------
__device__ __forceinline__ void bf_split(float v, unsigned short& h, unsigned short& l) {
    asm("cvt.rn.bf16.f32 %0, %1;" : "=h"(h) : "f"(v));
    float hf = __uint_as_float(((unsigned)h) << 16);
    float r = v - hf;
    asm("cvt.rn.bf16.f32 %0, %1;" : "=h"(l) : "f"(r));
}

__global__ void k_prep(const float* __restrict__ W1l, const float* __restrict__ W1r,
                       const float* __restrict__ W2l, const float* __restrict__ W2r) {
    int idx = blockIdx.x * blockDim.x + threadIdx.x;
    if (idx >= 128 * 256) return;
    int j = idx >> 8, k = idx & 255;
    float w1 = (k < 128) ? W1l[j * 128 + k] : W1r[j * 128 + (k - 128)];
    float w2 = (k < 128) ? W2l[j * 128 + k] : W2r[j * 128 + (k - 128)];
    unsigned short h, l;
    bf_split(w1, h, l); g_wh1[idx] = h; g_wl1[idx] = l;
    bf_split(w2, h, l); g_wh2[idx] = h; g_wl2[idx] = l;
}

// ---------------- bf16x2-split tensor-core GEMM (mma.sync HMMA) ----------------
// relu([Agg|Hin] @ W^T + b): M=100000 (block 128), N=128, K=256.
// BK=32; k-blocks 0-3 read Agg (k 0-127), 4-7 read Hin.
// Operands split v=hi+lo (bf16); accumulate hh+hl+lh in fp32 (ll ~2^-18, dropped).
// 8 warps = 2(M) x 4(N); warp tile 64x32; mma.m16n8k16.
// smem stride 40 bf16 (80B): 16B-aligned rows, conflict-free ldmatrix.

#define SSTR 40

__device__ __forceinline__ uint32_t smem_u32(const void* p) {
    uint32_t a;
    asm("{ .reg .u64 t; cvta.to.shared.u64 t, %1; cvt.u32.u64 %0, t; }" : "=r"(a) : "l"(p));
    return a;
}

__device__ __forceinline__ void ldsm_x4(unsigned* r, uint32_t a) {
    asm volatile("ldmatrix.sync.aligned.m8n8.x4.shared.b16 {%0,%1,%2,%3}, [%4];"
                 : "=r"(r[0]), "=r"(r[1]), "=r"(r[2]), "=r"(r[3]) : "r"(a));
}
__device__ __forceinline__ void ldsm_x2(unsigned* r, uint32_t a) {
    asm volatile("ldmatrix.sync.aligned.m8n8.x2.shared.b16 {%0,%1}, [%2];"
                 : "=r"(r[0]), "=r"(r[1]) : "r"(a));
}
__device__ __forceinline__ void mma_bf16(float* c, const unsigned* a, const unsigned* b) {
    asm volatile(
        "mma.sync.aligned.m16n8k16.row.col.f32.bf16.bf16.f32 "
        "{%0,%1,%2,%3}, {%4,%5,%6,%7}, {%8,%9}, {%0,%1,%2,%3};"
        : "+f"(c[0]), "+f"(c[1]), "+f"(c[2]), "+f"(c[3])
        : "r"(a[0]), "r"(a[1]), "r"(a[2]), "r"(a[3]), "r"(b[0]), "r"(b[1]));
}

__global__ void __launch_bounds__(256)
k_gemm_bf(const float* __restrict__ Agg, const float* __restrict__ Hin,
          const unsigned short* __restrict__ Wh, const unsigned short* __restrict__ Wl,
          const float* __restrict__ bias, float* __restrict__ Hout) {
    __shared__ __align__(16) unsigned short Ah[128 * SSTR], Al[128 * SSTR];
    __shared__ __align__(16) unsigned short Bh[128 * SSTR], Bl[128 * SSTR];
    __shared__ float bsm[128];
    int tid = threadIdx.x;
    int warp = tid >> 5, lane = tid & 31;
    int wm = warp & 1, wn = warp >> 1;        // 2 x 4 warp grid
    int gq = lane >> 2, tig = lane & 3;       // quad-pair layout
    int row0 = blockIdx.x * 128;
    if (tid < 128) bsm[tid] = bias[tid];

    // per-thread staging coords: 2 threads per row, 16 k each
    int srow = tid >> 1;
    int kseg = (tid & 1) * 16;
    // ldmatrix lane-address components
    int arow = (lane & 7) + 8 * ((lane >> 3) & 1);   // A x4 row within 16
    int akof = 8 * (lane >> 4);                      // A x4 k offset
    int brow = lane & 7;                             // B x2 row (n)
    int bkof = 8 * ((lane >> 3) & 1);                // B x2 k offset
    uint32_t ah_s = smem_u32(Ah), al_s = smem_u32(Al);
    uint32_t bh_s = smem_u32(Bh), bl_s = smem_u32(Bl);

    float acc[4][4][4];
#pragma unroll
    for (int mi = 0; mi < 4; mi++)
#pragma unroll
        for (int ni = 0; ni < 4; ni++)
#pragma unroll
            for (int r = 0; r < 4; r++) acc[mi][ni][r] = 0.f;

    for (int kb = 0; kb < 8; kb++) {
        int k0 = kb * 32;
        const float* S = (kb < 4) ? Agg : Hin;
        int kc = (k0 & 127) + kseg;
        // ---- stage A: split 16 fp32 -> bf16 hi/lo ----
        {
            int grow = row0 + srow;
            float v[16];
            if (grow < N_NODES) {
                const float4* p = (const float4*)(S + (size_t)grow * HIDF + kc);
#pragma unroll
                for (int q = 0; q < 4; q++) {
                    float4 f = p[q];
                    v[q * 4 + 0] = f.x; v[q * 4 + 1] = f.y;
                    v[q * 4 + 2] = f.z; v[q * 4 + 3] = f.w;
                }
            } else {
#pragma unroll
                for (int j = 0; j < 16; j++) v[j] = 0.f;
            }
            unsigned short hs[16], ls[16];
#pragma unroll
            for (int j = 0; j < 16; j++) bf_split(v[j], hs[j], ls[j]);
            uint4* dh = (uint4*)&Ah[srow * SSTR + kseg];
            uint4* dl = (uint4*)&Al[srow * SSTR + kseg];
#pragma unroll
            for (int half = 0; half < 2; half++) {
                uint4 hv, lv;
                int o = half * 8;
                hv.x = hs[o+0] | ((unsigned)hs[o+1] << 16);
                hv.y = hs[o+2] | ((unsigned)hs[o+3] << 16);
                hv.z = hs[o+4] | ((unsigned)hs[o+5] << 16);
                hv.w = hs[o+6] | ((unsigned)hs[o+7] << 16);
                lv.x = ls[o+0] | ((unsigned)ls[o+1] << 16);
                lv.y = ls[o+2] | ((unsigned)ls[o+3] << 16);
                lv.z = ls[o+4] | ((unsigned)ls[o+5] << 16);
                lv.w = ls[o+6] | ((unsigned)ls[o+7] << 16);
                dh[half] = hv;
                dl[half] = lv;
            }
        }
        // ---- stage B: bf16 hi/lo weights [n][256] ----
        {
            const uint4* ph = (const uint4*)(Wh + (size_t)srow * 256 + k0 + kseg);
            const uint4* pl = (const uint4*)(Wl + (size_t)srow * 256 + k0 + kseg);
            uint4* dh = (uint4*)&Bh[srow * SSTR + kseg];
            uint4* dl = (uint4*)&Bl[srow * SSTR + kseg];
            dh[0] = ph[0]; dh[1] = ph[1];
            dl[0] = pl[0]; dl[1] = pl[1];
        }
        __syncthreads();
        // ---- compute: 2 k16 steps ----
#pragma unroll
        for (int ks = 0; ks < 2; ks++) {
            int koff = ks * 16;
            unsigned ahf[4][4], alf[4][4], bhf[4][2], blf[4][2];
#pragma unroll
            for (int mi = 0; mi < 4; mi++) {
                uint32_t off = (uint32_t)(((wm * 64 + mi * 16 + arow) * SSTR + koff + akof) * 2);
                ldsm_x4(ahf[mi], ah_s + off);
                ldsm_x4(alf[mi], al_s + off);
            }
#pragma unroll
            for (int ni = 0; ni < 4; ni++) {
                uint32_t off = (uint32_t)(((wn * 32 + ni * 8 + brow) * SSTR + koff + bkof) * 2);
                ldsm_x2(bhf[ni], bh_s + off);
                ldsm_x2(blf[ni], bl_s + off);
            }
#pragma unroll
            for (int mi = 0; mi < 4; mi++)
#pragma unroll
                for (int ni = 0; ni < 4; ni++) {
                    mma_bf16(acc[mi][ni], ahf[mi], bhf[ni]);
                    mma_bf16(acc[mi][ni], ahf[mi], blf[ni]);
                    mma_bf16(acc[mi][ni], alf[mi], bhf[ni]);
                }
        }
        __syncthreads();
    }
    // ---- epilogue (layout verified in round 2) ----
#pragma unroll
    for (int mi = 0; mi < 4; mi++) {
#pragma unroll
        for (int ni = 0; ni < 4; ni++) {
            int colc = wn * 32 + ni * 8 + tig * 2;
            int ra = row0 + wm * 64 + mi * 16 + gq;
            int rb = ra + 8;
            if (ra < N_NODES) {
                float2 o;
                o.x = fmaxf(acc[mi][ni][0] + bsm[colc], 0.f);
                o.y = fmaxf(acc[mi][ni][1] + bsm[colc + 1], 0.f);
                *(float2*)(Hout + (size_t)ra * HIDF + colc) = o;
            }
            if (rb < N_NODES) {
                float2 o;
                o.x = fmaxf(acc[mi][ni][2] + bsm[colc], 0.f);
                o.y = fmaxf(acc[mi][ni][3] + bsm[colc + 1], 0.f);
                *(float2*)(Hout + (size_t)rb * HIDF + colc) = o;
            }
        }
    }
}

// ---------------- sorted segment-mean pooling ----------------
__global__ void k_pool(const float* __restrict__ H) {
    int t = threadIdx.x;
    int base = blockIdx.x * 512;
    if (base >= N_NODES) return;
    int end = min(base + 512, N_NODES);
    int cur = g_batch[base];
    float acc = 0.f;
    int run = 0;
    for (int n = base; n < end; n++) {
        int g = g_batch[n];
        if (g != cur) {
            atomicAdd(&g_pool[cur * HIDF + t], acc);
            if (t == 0) atomicAdd(&g_cnt[cur], run);
            acc = 0.f; run = 0; cur = g;
        }
        acc += H[(size_t)n * HIDF + t];
        run++;
    }
    atomicAdd(&g_pool[cur * HIDF + t], acc);
    if (t == 0) atomicAdd(&g_cnt[cur], run);
}

// ---------------- head ----------------
__global__ void k_head(const float* __restrict__ embed, const float* __restrict__ Wlin,
                       const float* __restrict__ blin, float* __restrict__ out) {
    int t = threadIdx.x;
    if (t >= N_GRAPHS * OUTF) return;
    int g = t >> 3, o = t & 7;
    float c = (float)max(g_cnt[g], 1);
    float inv = 1.0f / c;
    const float* wr = Wlin + o * (HIDF + EMBF);
    float s = 0.f;
    for (int k = 0; k < HIDF; k++) s += g_pool[g * HIDF + k] * inv * wr[k];
    for (int k = 0; k < EMBF; k++) s += embed[g * EMBF + k] * wr[HIDF + k];
    out[g * OUTF + o] = s + blin[o];
}

// ---------------- launch ----------------
extern "C" void kernel_launch(void* const* d_in, const int* in_sizes, int n_in,
                              void* d_out, int out_size) {
    const float* x     = (const float*)d_in[0];
    const void*  ei    = d_in[1];
    const void*  batch = d_in[2];
    const float* embed = (const float*)d_in[3];
    const float* W1l   = (const float*)d_in[4];
    const float* b1l   = (const float*)d_in[5];
    const float* W1r   = (const float*)d_in[6];
    const float* W2l   = (const float*)d_in[7];
    const float* b2l   = (const float*)d_in[8];
    const float* W2r   = (const float*)d_in[9];
    const float* Wlin  = (const float*)d_in[10];
    const float* blin  = (const float*)d_in[11];
    float* out = (float*)d_out;

    float *agg_p, *h1_p, *h2_p;
    unsigned short *wh1_p, *wl1_p, *wh2_p, *wl2_p;
    cudaGetSymbolAddress((void**)&agg_p, g_agg);
    cudaGetSymbolAddress((void**)&h1_p,  g_h1);
    cudaGetSymbolAddress((void**)&h2_p,  g_h2);
    cudaGetSymbolAddress((void**)&wh1_p, g_wh1);
    cudaGetSymbolAddress((void**)&wl1_p, g_wl1);
    cudaGetSymbolAddress((void**)&wh2_p, g_wh2);
    cudaGetSymbolAddress((void**)&wl2_p, g_wl2);

    const int TB = 256;
    k_detect<<<1, 256>>>((const unsigned int*)ei);
    k_convert_edges<<<(N_EDGES + TB - 1) / TB, TB>>>(ei);
    k_convert_batch<<<(N_NODES + TB - 1) / TB, TB>>>(batch);
    k_hist<<<(N_EDGES + TB - 1) / TB, TB>>>();
    k_scan<<<1, 1024>>>();
    k_fill<<<(N_EDGES + TB - 1) / TB, TB>>>();
    k_prep<<<(128 * 256 + TB - 1) / TB, TB>>>(W1l, W1r, W2l, W2r);

    const int NB = (N_NODES + 127) / 128;
    // layer 1
    k_aggregate<<<(N_NODES + 7) / 8, 256>>>(x, agg_p);
    k_gemm_bf<<<NB, 256>>>(agg_p, x, wh1_p, wl1_p, b1l, h1_p);
    // layer 2
    k_aggregate<<<(N_NODES + 7) / 8, 256>>>(h1_p, agg_p);
    k_gemm_bf<<<NB, 256>>>(agg_p, h1_p, wh2_p, wl2_p, b2l, h2_p);
    // pooling + head
    k_pool<<<(N_NODES + 511) / 512, 128>>>(h2_p);
    k_head<<<1, 512>>>(embed, Wlin, blin, out);
}